// round 3
// baseline (speedup 1.0000x reference)
#include <cuda_runtime.h>
#include <math.h>

// ---------------- problem constants ----------------
#define BN 32
#define CC 64
#define NN 307
#define TT 24
#define KT 3
#define NT (NN*TT)          // 7368
#define CNT (CC*NT)         // 471552
#define CT (CC*TT)          // 1536
#define N2 (NN*NN)          // 94249
#define KP 624              // padded 2*NN for GEMM (39*16)

static const long OUT0 = (long)BN*CNT;     // out
static const long SSZ  = (long)BN*N2;      // S_coef
static const long TSZ  = (long)BN*TT*TT;   // T_coef

// ---------------- scratch ----------------
__device__ float g_f1[BN*TT*NN];     // [b,t,n]
__device__ float g_g1[BN*NN*TT];     // [b,n,t]
__device__ float g_f2[BN*CC*TT];     // [b,c,t]
__device__ float g_g2[BN*CC*NN];     // [b,c,n]
__device__ float g_E [BN*NN*CC];     // SATT E: [b,p,c]
__device__ float g_Z [BN*N2];
__device__ float g_Z2[BN*N2];
__device__ float g_S [BN*N2];
__device__ float g_m [BN*NN];
__device__ float g_Tc[BN*TT*TT];
__device__ float g_L2[N2];
__device__ float g_A [ (long)BN*NN*KP ];   // Acat [b][q][kp], padded
__device__ float g_U0[(long)BN*NN*CT];     // k=0 weighted [b,n,o,t]
__device__ float g_U [(long)BN*2*NN*CT];   // k=1,2 rows
__device__ float g_sg[(long)BN*NN*CT];     // relu(gcn) [b,n,o,t]
__device__ float g_h [(long)BN*CC*NN*TT];  // pre-LN h [b,c,n,t]
__device__ float g_part[BN][NN][2];
__device__ float g_stats[BN][2];

// ---------------- feature kernels ----------------
__global__ void feat_c_kernel(const float* __restrict__ x,
                              const float* __restrict__ tc1,
                              const float* __restrict__ sc1) {
    int idx = blockIdx.x*256 + threadIdx.x;
    if (idx >= BN*NT) return;
    int b = idx / NT; int r = idx % NT; int n = r / TT; int t = r % TT;
    const float* xp = x + (long)b*CNT + r;
    float a1 = 0.f, a2 = 0.f;
    #pragma unroll 8
    for (int c = 0; c < CC; c++) {
        float v = xp[c*NT];
        a1 += v * __ldg(&tc1[c]);
        a2 += v * __ldg(&sc1[c]);
    }
    g_f1[(b*TT + t)*NN + n] = a1;
    g_g1[(b*NN + n)*TT + t] = a2;
}

__global__ void feat_f2_kernel(const float* __restrict__ x,
                               const float* __restrict__ tc2) {
    int b = blockIdx.y, c = blockIdx.x;
    __shared__ float part[240];
    int tid = threadIdx.x;
    const float* xp = x + (long)(b*CC + c)*NT;
    if (tid < 240) {
        int t = tid % TT; int ng = tid / TT;  // 0..9
        float a = 0.f;
        for (int n = ng; n < NN; n += 10) a += xp[n*TT + t] * __ldg(&tc2[n]);
        part[tid] = a;
    }
    __syncthreads();
    if (tid < TT) {
        float s = 0.f;
        #pragma unroll
        for (int g2 = 0; g2 < 10; g2++) s += part[g2*TT + tid];
        g_f2[(b*CC + c)*TT + tid] = s;
    }
}

__global__ void feat_g2_kernel(const float* __restrict__ x,
                               const float* __restrict__ sc2) {
    int idx = blockIdx.x*256 + threadIdx.x;
    if (idx >= BN*CC*NN) return;
    int n = idx % NN; int c = (idx/NN) % CC; int b = idx/(CC*NN);
    const float* xp = x + (long)(b*CC + c)*NT + n*TT;
    float a = 0.f;
    #pragma unroll
    for (int t = 0; t < TT; t++) a += xp[t] * __ldg(&sc2[t]);
    g_g2[idx] = a;
}

// ---------------- TATT ----------------
__global__ __launch_bounds__(256) void tatt_kernel(
    const float* __restrict__ tw, const float* __restrict__ tb,
    const float* __restrict__ tv, float* __restrict__ out, long osz) {
    int b = blockIdx.x;
    __shared__ float sf1[TT*NN];
    __shared__ float sf2[CC*TT];
    __shared__ float sE [TT*CC];
    __shared__ float slog[TT*TT];
    __shared__ float sl2 [TT*TT];
    __shared__ float sm  [TT];
    int tid = threadIdx.x;
    for (int i = tid; i < TT*NN; i += 256) sf1[i] = g_f1[b*TT*NN + i];
    for (int i = tid; i < CC*TT; i += 256) sf2[i] = g_f2[b*CC*TT + i];
    __syncthreads();
    for (int i = tid; i < TT*CC; i += 256) {
        int p = i / CC, c = i % CC;
        float a = 0.f;
        for (int n = 0; n < NN; n++) a += sf1[p*NN + n] * __ldg(&tw[n*CC + c]);
        sE[i] = a;
    }
    __syncthreads();
    for (int i = tid; i < TT*TT; i += 256) {
        int p = i / TT, q = i % TT;
        float a = tb[i];
        #pragma unroll 8
        for (int c = 0; c < CC; c++) a += sE[p*CC + c] * sf2[c*TT + q];
        slog[i] = 1.f / (1.f + expf(-a));
    }
    __syncthreads();
    for (int i = tid; i < TT*TT; i += 256) {
        int p = i / TT, q = i % TT;
        float a = 0.f;
        #pragma unroll
        for (int n = 0; n < TT; n++) a += __ldg(&tv[p*TT + n]) * slog[n*TT + q];
        sl2[i] = a;
    }
    __syncthreads();
    if (tid < TT) {
        float m = -1e30f;
        for (int p = 0; p < TT; p++) m = fmaxf(m, sl2[p*TT + tid]);
        sm[tid] = m;
    }
    __syncthreads();
    if (tid < TT) {
        int p = tid; float s = 0.f;
        for (int q = 0; q < TT; q++) { float e = expf(sl2[p*TT+q] - sm[q]); slog[p*TT+q] = e; s += e; }
        float inv = 1.f / s;
        for (int q = 0; q < TT; q++) slog[p*TT+q] *= inv;
    }
    __syncthreads();
    for (int i = tid; i < TT*TT; i += 256) {
        int l = i / TT, q = i % TT;
        float v = slog[q*TT + l];
        g_Tc[b*TT*TT + i] = v;
        if (osz >= OUT0 + SSZ + TSZ) out[OUT0 + SSZ + (long)b*TT*TT + i] = v;
    }
}

// ---------------- SATT E ----------------
__global__ void satt_E_kernel(const float* __restrict__ sw) {
    int idx = blockIdx.x*256 + threadIdx.x;
    if (idx >= BN*NN*CC) return;
    int c = idx % CC; int p = (idx/CC) % NN; int b = idx/(NN*CC);
    float a = 0.f;
    #pragma unroll
    for (int r = 0; r < TT; r++) a += g_g1[(b*NN + p)*TT + r] * __ldg(&sw[r*CC + c]);
    g_E[idx] = a;
}

// ---------------- generic 64x64 tiled GEMM (SATT, small) ----------------
__device__ __forceinline__ void gemm_core(
    const float* __restrict__ A, long asb,
    const float* __restrict__ Bm, long bsb,
    float* __restrict__ Cm, long csb,
    int M, int Np, int Kd, const float* __restrict__ biasM, int mode) {
    __shared__ float Ast[16][65];
    __shared__ float Bst[16][65];
    int b = blockIdx.z;
    const float* Ab = A + (long)b*asb;
    const float* Bb = Bm + (long)b*bsb;
    float* Cb = Cm + (long)b*csb;
    int m0 = blockIdx.y*64, n0 = blockIdx.x*64;
    int tid = threadIdx.x;
    int tx = tid & 15, ty = tid >> 4;
    float acc[4][4] = {};
    for (int kk = 0; kk < Kd; kk += 16) {
        #pragma unroll
        for (int i = 0; i < 4; i++) {
            int idx = tid + i*256; int r = idx >> 4, c = idx & 15;
            float v = 0.f;
            if (m0 + r < M && kk + c < Kd) v = Ab[(long)(m0+r)*Kd + kk + c];
            Ast[c][r] = v;
        }
        #pragma unroll
        for (int i = 0; i < 4; i++) {
            int idx = tid + i*256; int r = idx >> 6, c = idx & 63;
            float v = 0.f;
            if (kk + r < Kd && n0 + c < Np) v = Bb[(long)(kk+r)*Np + n0 + c];
            Bst[r][c] = v;
        }
        __syncthreads();
        #pragma unroll
        for (int k = 0; k < 16; k++) {
            float a[4], bb[4];
            #pragma unroll
            for (int i = 0; i < 4; i++) a[i] = Ast[k][ty*4 + i];
            #pragma unroll
            for (int j = 0; j < 4; j++) bb[j] = Bst[k][tx*4 + j];
            #pragma unroll
            for (int i = 0; i < 4; i++)
                #pragma unroll
                for (int j = 0; j < 4; j++) acc[i][j] += a[i]*bb[j];
        }
        __syncthreads();
    }
    #pragma unroll
    for (int i = 0; i < 4; i++) {
        int r = m0 + ty*4 + i;
        if (r >= M) continue;
        #pragma unroll
        for (int j = 0; j < 4; j++) {
            int c = n0 + tx*4 + j;
            if (c >= Np) continue;
            float v = acc[i][j];
            if (mode == 1) v = 2.f*v - (r == c ? 1.f : 0.f);
            else if (mode == 2) v = 1.f/(1.f + expf(-(v + biasM[(long)r*Np + c])));
            Cb[(long)r*Np + c] = v;
        }
    }
}

__global__ __launch_bounds__(256) void gemm_Z_kernel(const float* __restrict__ sb) {
    gemm_core(g_E, (long)NN*CC, g_g2, (long)CC*NN, g_Z, (long)N2, NN, NN, CC, sb, 2);
}
__global__ __launch_bounds__(256) void gemm_Z2_kernel(const float* __restrict__ sv) {
    gemm_core(sv, 0, g_Z, (long)N2, g_Z2, (long)N2, NN, NN, NN, nullptr, 0);
}
__global__ __launch_bounds__(256) void gemm_cheb_kernel(const float* __restrict__ sup) {
    gemm_core(sup, 0, sup, 0, g_L2, 0, NN, NN, NN, nullptr, 1);
}

// ---------------- SATT colmax + softmax ----------------
__global__ void colmax_kernel() {
    int b = blockIdx.x; int q = threadIdx.x;
    if (q >= NN) return;
    const float* Z2b = g_Z2 + (long)b*N2;
    float m = -1e30f;
    for (int p = 0; p < NN; p++) m = fmaxf(m, Z2b[p*NN + q]);
    g_m[b*NN + q] = m;
}

__global__ void softmax_kernel(float* __restrict__ out, long osz) {
    int b = blockIdx.y, p = blockIdx.x;
    const float* row = g_Z2 + ((long)b*NN + p)*NN;
    const float* mv = g_m + b*NN;
    __shared__ float se[NN];
    __shared__ float red[128];
    int tid = threadIdx.x;
    float s = 0.f;
    for (int q = tid; q < NN; q += 128) { float e = expf(row[q] - mv[q]); se[q] = e; s += e; }
    red[tid] = s; __syncthreads();
    for (int o = 64; o > 0; o >>= 1) { if (tid < o) red[tid] += red[tid + o]; __syncthreads(); }
    float inv = 1.f / red[0];
    float* Sb = g_S + ((long)b*NN + p)*NN;
    for (int q = tid; q < NN; q += 128) {
        float v = se[q]*inv;
        Sb[q] = v;
        if (osz >= OUT0 + SSZ) out[OUT0 + ((long)b*NN + p)*NN + q] = v;
    }
}

// ---------------- Acat precompute ----------------
__global__ void acat_kernel(const float* __restrict__ sup) {
    long idx = (long)blockIdx.x*256 + threadIdx.x;
    long total = (long)BN*NN*KP;
    if (idx >= total) return;
    int kp = (int)(idx % KP); long r = idx / KP;
    int q = (int)(r % NN); int b = (int)(r / NN);
    float v = 0.f;
    if (kp < NN) {
        v = g_S[((long)b*NN + q)*NN + kp] * __ldg(&sup[q*NN + kp]);
    } else if (kp < 2*NN) {
        int n = kp - NN;
        v = g_S[((long)b*NN + q)*NN + n] * g_L2[q*NN + n];
    }
    g_A[idx] = v;
}

// ---------------- fused x_TAt + gcn-weighted U ----------------
__global__ __launch_bounds__(256) void xtat_u_kernel(const float* __restrict__ x,
                                                     const float* __restrict__ gcnw) {
    int b = blockIdx.y, n = blockIdx.x;
    __shared__ float xs[CT];
    __shared__ float tc[TT*TT];
    __shared__ float xt[CT];
    int tid = threadIdx.x;
    for (int i = tid; i < CT; i += 256) {
        int c = i / TT, t = i % TT;
        xs[i] = x[((long)(b*CC + c)*NN + n)*TT + t];
    }
    for (int i = tid; i < TT*TT; i += 256) tc[i] = g_Tc[b*TT*TT + i];
    __syncthreads();
    for (int i = tid; i < CT; i += 256) {
        int c = i / TT, q = i % TT;
        float a = 0.f;
        #pragma unroll
        for (int l = 0; l < TT; l++) a += xs[c*TT + l] * tc[l*TT + q];
        xt[i] = a;
    }
    __syncthreads();
    int o = tid >> 2;
    int t0 = (tid & 3) * 6;
    float a0[6] = {}, a1[6] = {}, a2[6] = {};
    const float* wrow = gcnw + o*(KT*CC);
    for (int c = 0; c < CC; c++) {
        float w0 = __ldg(&wrow[c*3 + 0]);
        float w1 = __ldg(&wrow[c*3 + 1]);
        float w2 = __ldg(&wrow[c*3 + 2]);
        const float* xp = &xt[c*TT + t0];
        #pragma unroll
        for (int j = 0; j < 6; j++) {
            float xv = xp[j];
            a0[j] += w0*xv; a1[j] += w1*xv; a2[j] += w2*xv;
        }
    }
    long off = o*TT + t0;
    float* u0 = g_U0 + ((long)b*NN + n)*CT + off;
    float* u1 = g_U  + ((long)b*2*NN + n)*CT + off;
    float* u2 = g_U  + ((long)b*2*NN + NN + n)*CT + off;
    #pragma unroll
    for (int j = 0; j < 6; j++) { u0[j] = a0[j]; u1[j] = a1[j]; u2[j] = a2[j]; }
}

// ---------------- big graph GEMM: 128x128x16, 8x8/thread, double-buffered ----
__global__ __launch_bounds__(256) void gemm_graph_kernel(const float* __restrict__ gcnb) {
    __shared__ float As[2][16][132];
    __shared__ float Bs[2][16][132];
    int b = blockIdx.z;
    int m0 = blockIdx.y*128, n0 = blockIdx.x*128;
    const float* Ab = g_A + (long)b*NN*KP;
    const float* Ub = g_U + (long)b*(2*NN)*CT;
    int tid = threadIdx.x;
    int arow = tid >> 2, acol = (tid & 3) * 4;
    int brow = tid >> 5, bcol = (tid & 31) * 4;
    float4 ra[2], rb[2];
    const float4 fz = make_float4(0.f, 0.f, 0.f, 0.f);
    // prologue (kk = 0)
    #pragma unroll
    for (int i = 0; i < 2; i++) {
        int row = m0 + arow + i*64;
        ra[i] = (row < NN) ? *(const float4*)(Ab + (long)row*KP + acol) : fz;
        int kp = brow + i*8;
        rb[i] = (kp < 2*NN) ? *(const float4*)(Ub + (long)kp*CT + n0 + bcol) : fz;
    }
    #pragma unroll
    for (int i = 0; i < 2; i++) {
        float* ap = &As[0][acol][arow + i*64];
        ap[0] = ra[i].x; ap[132] = ra[i].y; ap[264] = ra[i].z; ap[396] = ra[i].w;
        *(float4*)&Bs[0][brow + i*8][bcol] = rb[i];
    }
    __syncthreads();
    int ty = tid >> 4, tx = tid & 15;
    float acc[8][8] = {};
    for (int step = 0; step < 39; step++) {
        if (step < 38) {
            int kk = (step + 1) * 16;
            #pragma unroll
            for (int i = 0; i < 2; i++) {
                int row = m0 + arow + i*64;
                ra[i] = (row < NN) ? *(const float4*)(Ab + (long)row*KP + kk + acol) : fz;
                int kp = kk + brow + i*8;
                rb[i] = (kp < 2*NN) ? *(const float4*)(Ub + (long)kp*CT + n0 + bcol) : fz;
            }
        }
        int buf = step & 1;
        #pragma unroll
        for (int k = 0; k < 16; k++) {
            float a[8], bb[8];
            *(float4*)&a[0]  = *(const float4*)&As[buf][k][ty*8];
            *(float4*)&a[4]  = *(const float4*)&As[buf][k][ty*8 + 4];
            *(float4*)&bb[0] = *(const float4*)&Bs[buf][k][tx*8];
            *(float4*)&bb[4] = *(const float4*)&Bs[buf][k][tx*8 + 4];
            #pragma unroll
            for (int i = 0; i < 8; i++)
                #pragma unroll
                for (int j = 0; j < 8; j++) acc[i][j] += a[i]*bb[j];
        }
        if (step < 38) {
            int nb = buf ^ 1;
            #pragma unroll
            for (int i = 0; i < 2; i++) {
                float* ap = &As[nb][acol][arow + i*64];
                ap[0] = ra[i].x; ap[132] = ra[i].y; ap[264] = ra[i].z; ap[396] = ra[i].w;
                *(float4*)&Bs[nb][brow + i*8][bcol] = rb[i];
            }
        }
        __syncthreads();
    }
    const float* Sb  = g_S  + (long)b*N2;
    const float* U0b = g_U0 + (long)b*NN*CT;
    float* sgb = g_sg + (long)b*NN*CT;
    #pragma unroll
    for (int i = 0; i < 8; i++) {
        int q = m0 + ty*8 + i;
        if (q >= NN) continue;
        float sd = Sb[(long)q*NN + q];
        const float* u0r = U0b + (long)q*CT;
        float* sgr = sgb + (long)q*CT;
        #pragma unroll
        for (int j = 0; j < 8; j++) {
            int cidx = n0 + tx*8 + j;
            float v = acc[i][j] + sd*u0r[cidx] + __ldg(&gcnb[cidx/TT]);
            sgr[cidx] = fmaxf(v, 0.f);
        }
    }
}

// ---------------- tconv + residual conv + relu + LN partials ----------
#define TCN 2
__global__ __launch_bounds__(256) void tconv_kernel(
    const float* __restrict__ x,
    const float* __restrict__ c1w, const float* __restrict__ c1b,
    const float* __restrict__ tcw, const float* __restrict__ tcb) {
    int b = blockIdx.y;
    int n0 = blockIdx.x*TCN;
    __shared__ float ss[TCN][CC][28];
    __shared__ float xs[TCN][CT];
    __shared__ float redS[TCN][4], redQ[TCN][4];
    int tid = threadIdx.x;
    int g = tid >> 7;       // 0..1
    int lane = tid & 127;
    int n = n0 + g;
    if (n < NN) {
        const float* sgb = g_sg + ((long)b*NN + n)*CT;
        for (int i = lane; i < CT; i += 128) {
            int c = i / TT, t = i % TT;
            ss[g][c][t + 1] = sgb[i];
        }
        if (lane < CC) { ss[g][lane][0] = 0.f; ss[g][lane][25] = 0.f; }
        for (int i = lane; i < CT; i += 128) {
            int c = i / TT, t = i % TT;
            xs[g][i] = x[((long)(b*CC + c)*NN + n)*TT + t];
        }
    }
    __syncthreads();
    int og = lane >> 2;          // 0..31
    int t0 = (lane & 3) * 6;
    float acc[2][6];
    #pragma unroll
    for (int i = 0; i < 2; i++) {
        int o = og*2 + i;
        float bias = __ldg(&tcb[o]) + __ldg(&c1b[o]);
        #pragma unroll
        for (int j = 0; j < 6; j++) acc[i][j] = bias;
    }
    float lsum = 0.f, lsq = 0.f;
    if (n < NN) {
        for (int c = 0; c < CC; c++) {
            float s[8];
            #pragma unroll
            for (int j = 0; j < 8; j++) s[j] = ss[g][c][t0 + j];
            float xv[6];
            #pragma unroll
            for (int j = 0; j < 6; j++) xv[j] = xs[g][c*TT + t0 + j];
            #pragma unroll
            for (int i = 0; i < 2; i++) {
                int o = og*2 + i;
                float w0 = __ldg(&tcw[o*192 + c*3 + 0]);
                float w1 = __ldg(&tcw[o*192 + c*3 + 1]);
                float w2 = __ldg(&tcw[o*192 + c*3 + 2]);
                float cw = __ldg(&c1w[o*CC + c]);
                #pragma unroll
                for (int j = 0; j < 6; j++)
                    acc[i][j] += w0*s[j] + w1*s[j+1] + w2*s[j+2] + cw*xv[j];
            }
        }
        #pragma unroll
        for (int i = 0; i < 2; i++) {
            int o = og*2 + i;
            float* hp = g_h + ((long)(b*CC + o)*NN + n)*TT + t0;
            #pragma unroll
            for (int j = 0; j < 6; j++) {
                float h = fmaxf(acc[i][j], 0.f);
                hp[j] = h;
                lsum += h; lsq += h*h;
            }
        }
    }
    #pragma unroll
    for (int o2 = 16; o2 > 0; o2 >>= 1) {
        lsum += __shfl_down_sync(0xffffffffu, lsum, o2);
        lsq  += __shfl_down_sync(0xffffffffu, lsq,  o2);
    }
    if ((lane & 31) == 0) { redS[g][lane >> 5] = lsum; redQ[g][lane >> 5] = lsq; }
    __syncthreads();
    if (lane == 0 && n < NN) {
        float s = 0.f, q2 = 0.f;
        #pragma unroll
        for (int w = 0; w < 4; w++) { s += redS[g][w]; q2 += redQ[g][w]; }
        g_part[b][n][0] = s; g_part[b][n][1] = q2;
    }
}

// ---------------- LN stats + apply ----------------
__global__ void stats_kernel() {
    int b = blockIdx.x; int tid = threadIdx.x;
    __shared__ float rs[256], rq[256];
    float s = 0.f, q = 0.f;
    for (int n = tid; n < NN; n += 256) { s += g_part[b][n][0]; q += g_part[b][n][1]; }
    rs[tid] = s; rq[tid] = q; __syncthreads();
    for (int o = 128; o > 0; o >>= 1) {
        if (tid < o) { rs[tid] += rs[tid + o]; rq[tid] += rq[tid + o]; }
        __syncthreads();
    }
    if (tid == 0) {
        float mu = rs[0] / (float)CNT;
        float var = rq[0] / (float)CNT - mu*mu;
        g_stats[b][0] = mu;
        g_stats[b][1] = rsqrtf(var + 1e-5f);
    }
}

__global__ void ln_kernel(const float* __restrict__ lng,
                          const float* __restrict__ lnb,
                          float* __restrict__ out) {
    long idx = (long)blockIdx.x*256 + threadIdx.x;
    if (idx >= OUT0) return;
    int b = (int)(idx / CNT);
    int r = (int)(idx % CNT);
    float mu = g_stats[b][0], rstd = g_stats[b][1];
    out[idx] = (g_h[idx] - mu)*rstd*__ldg(&lng[r]) + __ldg(&lnb[r]);
}

// ---------------- launch ----------------
extern "C" void kernel_launch(void* const* d_in, const int* in_sizes, int n_in,
                              void* d_out, int out_size) {
    const float* x       = (const float*)d_in[0];
    const float* supports= (const float*)d_in[1];
    const float* conv1_w = (const float*)d_in[2];
    const float* conv1_b = (const float*)d_in[3];
    const float* t_c1    = (const float*)d_in[4];
    const float* t_c2    = (const float*)d_in[5];
    const float* t_w     = (const float*)d_in[6];
    const float* t_b     = (const float*)d_in[7];
    const float* t_v     = (const float*)d_in[8];
    const float* s_c1    = (const float*)d_in[9];
    const float* s_c2    = (const float*)d_in[10];
    const float* s_w     = (const float*)d_in[11];
    const float* s_b     = (const float*)d_in[12];
    const float* s_v     = (const float*)d_in[13];
    const float* gcn_w   = (const float*)d_in[14];
    const float* gcn_b   = (const float*)d_in[15];
    const float* tc_w    = (const float*)d_in[16];
    const float* tc_b    = (const float*)d_in[17];
    const float* ln_g    = (const float*)d_in[18];
    const float* ln_b    = (const float*)d_in[19];
    float* out = (float*)d_out;
    long osz = (long)out_size;

    // features
    feat_c_kernel <<<(BN*NT + 255)/256, 256>>>(x, t_c1, s_c1);
    feat_f2_kernel<<<dim3(CC, BN), 256>>>(x, t_c2);
    feat_g2_kernel<<<(BN*CC*NN + 255)/256, 256>>>(x, s_c2);

    // temporal attention
    tatt_kernel<<<BN, 256>>>(t_w, t_b, t_v, out, osz);

    // spatial attention
    satt_E_kernel<<<(BN*NN*CC + 255)/256, 256>>>(s_w);
    dim3 gz((NN + 63)/64, (NN + 63)/64, BN);
    gemm_Z_kernel <<<gz, 256>>>(s_b);
    gemm_Z2_kernel<<<gz, 256>>>(s_v);
    colmax_kernel<<<BN, 320>>>();
    softmax_kernel<<<dim3(NN, BN), 128>>>(out, osz);

    // Chebyshev L2
    dim3 gc((NN + 63)/64, (NN + 63)/64, 1);
    gemm_cheb_kernel<<<gc, 256>>>(supports);

    // Acat precompute
    {
        long total = (long)BN*NN*KP;
        acat_kernel<<<(int)((total + 255)/256), 256>>>(supports);
    }

    // fused x_TAt + U
    xtat_u_kernel<<<dim3(NN, BN), 256>>>(x, gcn_w);

    // big graph GEMM: per-b [307 x 614] @ [614 x 1536], fused epilogue
    dim3 gg(CT/128, (NN + 127)/128, BN);
    gemm_graph_kernel<<<gg, 256>>>(gcn_b);

    // tconv + residual + relu + LN partials
    tconv_kernel<<<dim3((NN + TCN - 1)/TCN, BN), 256>>>(x, conv1_w, conv1_b, tc_w, tc_b);

    // LayerNorm
    stats_kernel<<<BN, 256>>>();
    ln_kernel<<<(int)((OUT0 + 255)/256), 256>>>(ln_g, ln_b, out);
}

// round 4
// speedup vs baseline: 1.0007x; 1.0007x over previous
#include <cuda_runtime.h>
#include <math.h>

// ---------------- problem constants ----------------
#define BN 32
#define CC 64
#define NN 307
#define TT 24
#define KT 3
#define NT (NN*TT)          // 7368
#define CNT (CC*NT)         // 471552
#define CT (CC*TT)          // 1536
#define N2 (NN*NN)          // 94249
#define KP 624              // padded 2*NN for GEMM (39*16)

static const long OUT0 = (long)BN*CNT;     // out
static const long SSZ  = (long)BN*N2;      // S_coef
static const long TSZ  = (long)BN*TT*TT;   // T_coef

// ---------------- scratch ----------------
__device__ float g_f1[BN*TT*NN];     // [b,t,n]
__device__ float g_g1[BN*NN*TT];     // [b,n,t]
__device__ float g_f2[BN*CC*TT];     // [b,c,t]
__device__ float g_g2[BN*CC*NN];     // [b,c,n]
__device__ float g_E [BN*NN*CC];     // SATT E: [b,p,c]
__device__ float g_Z [BN*N2];
__device__ float g_Z2[BN*N2];
__device__ float g_S [BN*N2];
__device__ float g_m [BN*NN];
__device__ float g_Tc[BN*TT*TT];
__device__ float g_L2[N2];
__device__ float g_A [ (long)BN*NN*KP ];   // Acat [b][q][kp], padded
__device__ float g_U0[(long)BN*NN*CT];     // k=0 weighted [b,n,o,t]
__device__ float g_U [(long)BN*2*NN*CT];   // k=1,2 rows
__device__ float g_sg[(long)BN*NN*CT];     // relu(gcn) [b,n,o,t]
__device__ float g_h [(long)BN*CC*NN*TT];  // pre-LN h [b,c,n,t]
__device__ float g_part[BN][NN][2];
__device__ float g_stats[BN][2];

// ---------------- feature kernels ----------------
__global__ void feat_c_kernel(const float* __restrict__ x,
                              const float* __restrict__ tc1,
                              const float* __restrict__ sc1) {
    int idx = blockIdx.x*256 + threadIdx.x;
    if (idx >= BN*NT) return;
    int b = idx / NT; int r = idx % NT; int n = r / TT; int t = r % TT;
    const float* xp = x + (long)b*CNT + r;
    float a1 = 0.f, a2 = 0.f;
    #pragma unroll 8
    for (int c = 0; c < CC; c++) {
        float v = xp[c*NT];
        a1 += v * __ldg(&tc1[c]);
        a2 += v * __ldg(&sc1[c]);
    }
    g_f1[(b*TT + t)*NN + n] = a1;
    g_g1[(b*NN + n)*TT + t] = a2;
}

__global__ void feat_f2_kernel(const float* __restrict__ x,
                               const float* __restrict__ tc2) {
    int b = blockIdx.y, c = blockIdx.x;
    __shared__ float part[240];
    int tid = threadIdx.x;
    const float* xp = x + (long)(b*CC + c)*NT;
    if (tid < 240) {
        int t = tid % TT; int ng = tid / TT;  // 0..9
        float a = 0.f;
        for (int n = ng; n < NN; n += 10) a += xp[n*TT + t] * __ldg(&tc2[n]);
        part[tid] = a;
    }
    __syncthreads();
    if (tid < TT) {
        float s = 0.f;
        #pragma unroll
        for (int g2 = 0; g2 < 10; g2++) s += part[g2*TT + tid];
        g_f2[(b*CC + c)*TT + tid] = s;
    }
}

__global__ void feat_g2_kernel(const float* __restrict__ x,
                               const float* __restrict__ sc2) {
    int idx = blockIdx.x*256 + threadIdx.x;
    if (idx >= BN*CC*NN) return;
    int n = idx % NN; int c = (idx/NN) % CC; int b = idx/(CC*NN);
    const float* xp = x + (long)(b*CC + c)*NT + n*TT;
    float a = 0.f;
    #pragma unroll
    for (int t = 0; t < TT; t++) a += xp[t] * __ldg(&sc2[t]);
    g_g2[idx] = a;
}

// ---------------- TATT ----------------
__global__ __launch_bounds__(256) void tatt_kernel(
    const float* __restrict__ tw, const float* __restrict__ tb,
    const float* __restrict__ tv, float* __restrict__ out, long osz) {
    int b = blockIdx.x;
    __shared__ float sf1[TT*NN];
    __shared__ float sf2[CC*TT];
    __shared__ float sE [TT*CC];
    __shared__ float slog[TT*TT];
    __shared__ float sl2 [TT*TT];
    __shared__ float sm  [TT];
    int tid = threadIdx.x;
    for (int i = tid; i < TT*NN; i += 256) sf1[i] = g_f1[b*TT*NN + i];
    for (int i = tid; i < CC*TT; i += 256) sf2[i] = g_f2[b*CC*TT + i];
    __syncthreads();
    for (int i = tid; i < TT*CC; i += 256) {
        int p = i / CC, c = i % CC;
        float a = 0.f;
        for (int n = 0; n < NN; n++) a += sf1[p*NN + n] * __ldg(&tw[n*CC + c]);
        sE[i] = a;
    }
    __syncthreads();
    for (int i = tid; i < TT*TT; i += 256) {
        int p = i / TT, q = i % TT;
        float a = tb[i];
        #pragma unroll 8
        for (int c = 0; c < CC; c++) a += sE[p*CC + c] * sf2[c*TT + q];
        slog[i] = 1.f / (1.f + expf(-a));
    }
    __syncthreads();
    for (int i = tid; i < TT*TT; i += 256) {
        int p = i / TT, q = i % TT;
        float a = 0.f;
        #pragma unroll
        for (int n = 0; n < TT; n++) a += __ldg(&tv[p*TT + n]) * slog[n*TT + q];
        sl2[i] = a;
    }
    __syncthreads();
    if (tid < TT) {
        float m = -1e30f;
        for (int p = 0; p < TT; p++) m = fmaxf(m, sl2[p*TT + tid]);
        sm[tid] = m;
    }
    __syncthreads();
    if (tid < TT) {
        int p = tid; float s = 0.f;
        for (int q = 0; q < TT; q++) { float e = expf(sl2[p*TT+q] - sm[q]); slog[p*TT+q] = e; s += e; }
        float inv = 1.f / s;
        for (int q = 0; q < TT; q++) slog[p*TT+q] *= inv;
    }
    __syncthreads();
    for (int i = tid; i < TT*TT; i += 256) {
        int l = i / TT, q = i % TT;
        float v = slog[q*TT + l];
        g_Tc[b*TT*TT + i] = v;
        if (osz >= OUT0 + SSZ + TSZ) out[OUT0 + SSZ + (long)b*TT*TT + i] = v;
    }
}

// ---------------- SATT E ----------------
__global__ void satt_E_kernel(const float* __restrict__ sw) {
    int idx = blockIdx.x*256 + threadIdx.x;
    if (idx >= BN*NN*CC) return;
    int c = idx % CC; int p = (idx/CC) % NN; int b = idx/(NN*CC);
    float a = 0.f;
    #pragma unroll
    for (int r = 0; r < TT; r++) a += g_g1[(b*NN + p)*TT + r] * __ldg(&sw[r*CC + c]);
    g_E[idx] = a;
}

// ---------------- generic 64x64 tiled GEMM (SATT, small) ----------------
__device__ __forceinline__ void gemm_core(
    const float* __restrict__ A, long asb,
    const float* __restrict__ Bm, long bsb,
    float* __restrict__ Cm, long csb,
    int M, int Np, int Kd, const float* __restrict__ biasM, int mode) {
    __shared__ float Ast[16][65];
    __shared__ float Bst[16][65];
    int b = blockIdx.z;
    const float* Ab = A + (long)b*asb;
    const float* Bb = Bm + (long)b*bsb;
    float* Cb = Cm + (long)b*csb;
    int m0 = blockIdx.y*64, n0 = blockIdx.x*64;
    int tid = threadIdx.x;
    int tx = tid & 15, ty = tid >> 4;
    float acc[4][4] = {};
    for (int kk = 0; kk < Kd; kk += 16) {
        #pragma unroll
        for (int i = 0; i < 4; i++) {
            int idx = tid + i*256; int r = idx >> 4, c = idx & 15;
            float v = 0.f;
            if (m0 + r < M && kk + c < Kd) v = Ab[(long)(m0+r)*Kd + kk + c];
            Ast[c][r] = v;
        }
        #pragma unroll
        for (int i = 0; i < 4; i++) {
            int idx = tid + i*256; int r = idx >> 6, c = idx & 63;
            float v = 0.f;
            if (kk + r < Kd && n0 + c < Np) v = Bb[(long)(kk+r)*Np + n0 + c];
            Bst[r][c] = v;
        }
        __syncthreads();
        #pragma unroll
        for (int k = 0; k < 16; k++) {
            float a[4], bb[4];
            #pragma unroll
            for (int i = 0; i < 4; i++) a[i] = Ast[k][ty*4 + i];
            #pragma unroll
            for (int j = 0; j < 4; j++) bb[j] = Bst[k][tx*4 + j];
            #pragma unroll
            for (int i = 0; i < 4; i++)
                #pragma unroll
                for (int j = 0; j < 4; j++) acc[i][j] += a[i]*bb[j];
        }
        __syncthreads();
    }
    #pragma unroll
    for (int i = 0; i < 4; i++) {
        int r = m0 + ty*4 + i;
        if (r >= M) continue;
        #pragma unroll
        for (int j = 0; j < 4; j++) {
            int c = n0 + tx*4 + j;
            if (c >= Np) continue;
            float v = acc[i][j];
            if (mode == 1) v = 2.f*v - (r == c ? 1.f : 0.f);
            else if (mode == 2) v = 1.f/(1.f + expf(-(v + biasM[(long)r*Np + c])));
            Cb[(long)r*Np + c] = v;
        }
    }
}

__global__ __launch_bounds__(256) void gemm_Z_kernel(const float* __restrict__ sb) {
    gemm_core(g_E, (long)NN*CC, g_g2, (long)CC*NN, g_Z, (long)N2, NN, NN, CC, sb, 2);
}
__global__ __launch_bounds__(256) void gemm_Z2_kernel(const float* __restrict__ sv) {
    gemm_core(sv, 0, g_Z, (long)N2, g_Z2, (long)N2, NN, NN, NN, nullptr, 0);
}
__global__ __launch_bounds__(256) void gemm_cheb_kernel(const float* __restrict__ sup) {
    gemm_core(sup, 0, sup, 0, g_L2, 0, NN, NN, NN, nullptr, 1);
}

// ---------------- SATT colmax + softmax ----------------
__global__ void colmax_kernel() {
    int b = blockIdx.x; int q = threadIdx.x;
    if (q >= NN) return;
    const float* Z2b = g_Z2 + (long)b*N2;
    float m = -1e30f;
    for (int p = 0; p < NN; p++) m = fmaxf(m, Z2b[p*NN + q]);
    g_m[b*NN + q] = m;
}

__global__ void softmax_kernel(float* __restrict__ out, long osz) {
    int b = blockIdx.y, p = blockIdx.x;
    const float* row = g_Z2 + ((long)b*NN + p)*NN;
    const float* mv = g_m + b*NN;
    __shared__ float se[NN];
    __shared__ float red[128];
    int tid = threadIdx.x;
    float s = 0.f;
    for (int q = tid; q < NN; q += 128) { float e = expf(row[q] - mv[q]); se[q] = e; s += e; }
    red[tid] = s; __syncthreads();
    for (int o = 64; o > 0; o >>= 1) { if (tid < o) red[tid] += red[tid + o]; __syncthreads(); }
    float inv = 1.f / red[0];
    float* Sb = g_S + ((long)b*NN + p)*NN;
    for (int q = tid; q < NN; q += 128) {
        float v = se[q]*inv;
        Sb[q] = v;
        if (osz >= OUT0 + SSZ) out[OUT0 + ((long)b*NN + p)*NN + q] = v;
    }
}

// ---------------- Acat precompute ----------------
__global__ void acat_kernel(const float* __restrict__ sup) {
    long idx = (long)blockIdx.x*256 + threadIdx.x;
    long total = (long)BN*NN*KP;
    if (idx >= total) return;
    int kp = (int)(idx % KP); long r = idx / KP;
    int q = (int)(r % NN); int b = (int)(r / NN);
    float v = 0.f;
    if (kp < NN) {
        v = g_S[((long)b*NN + q)*NN + kp] * __ldg(&sup[q*NN + kp]);
    } else if (kp < 2*NN) {
        int n = kp - NN;
        v = g_S[((long)b*NN + q)*NN + n] * g_L2[q*NN + n];
    }
    g_A[idx] = v;
}

// ---------------- fused x_TAt + gcn-weighted U ----------------
__global__ __launch_bounds__(256) void xtat_u_kernel(const float* __restrict__ x,
                                                     const float* __restrict__ gcnw) {
    int b = blockIdx.y, n = blockIdx.x;
    __shared__ float xs[CT];
    __shared__ float tc[TT*TT];
    __shared__ float xt[CT];
    int tid = threadIdx.x;
    for (int i = tid; i < CT; i += 256) {
        int c = i / TT, t = i % TT;
        xs[i] = x[((long)(b*CC + c)*NN + n)*TT + t];
    }
    for (int i = tid; i < TT*TT; i += 256) tc[i] = g_Tc[b*TT*TT + i];
    __syncthreads();
    for (int i = tid; i < CT; i += 256) {
        int c = i / TT, q = i % TT;
        float a = 0.f;
        #pragma unroll
        for (int l = 0; l < TT; l++) a += xs[c*TT + l] * tc[l*TT + q];
        xt[i] = a;
    }
    __syncthreads();
    int o = tid >> 2;
    int t0 = (tid & 3) * 6;
    float a0[6] = {}, a1[6] = {}, a2[6] = {};
    const float* wrow = gcnw + o*(KT*CC);
    for (int c = 0; c < CC; c++) {
        float w0 = __ldg(&wrow[c*3 + 0]);
        float w1 = __ldg(&wrow[c*3 + 1]);
        float w2 = __ldg(&wrow[c*3 + 2]);
        const float* xp = &xt[c*TT + t0];
        #pragma unroll
        for (int j = 0; j < 6; j++) {
            float xv = xp[j];
            a0[j] += w0*xv; a1[j] += w1*xv; a2[j] += w2*xv;
        }
    }
    long off = o*TT + t0;
    float* u0 = g_U0 + ((long)b*NN + n)*CT + off;
    float* u1 = g_U  + ((long)b*2*NN + n)*CT + off;
    float* u2 = g_U  + ((long)b*2*NN + NN + n)*CT + off;
    #pragma unroll
    for (int j = 0; j < 6; j++) { u0[j] = a0[j]; u1[j] = a1[j]; u2[j] = a2[j]; }
}

// ---------------- big graph GEMM: 128x128x16, 8x8/thread, double-buffered ----
__global__ __launch_bounds__(256) void gemm_graph_kernel(const float* __restrict__ gcnb) {
    __shared__ float As[2][16][132];
    __shared__ float Bs[2][16][132];
    int b = blockIdx.z;
    int m0 = blockIdx.y*128, n0 = blockIdx.x*128;
    const float* Ab = g_A + (long)b*NN*KP;
    const float* Ub = g_U + (long)b*(2*NN)*CT;
    int tid = threadIdx.x;
    int arow = tid >> 2, acol = (tid & 3) * 4;
    int brow = tid >> 5, bcol = (tid & 31) * 4;
    float4 ra[2], rb[2];
    const float4 fz = make_float4(0.f, 0.f, 0.f, 0.f);
    // prologue (kk = 0)
    #pragma unroll
    for (int i = 0; i < 2; i++) {
        int row = m0 + arow + i*64;
        ra[i] = (row < NN) ? *(const float4*)(Ab + (long)row*KP + acol) : fz;
        int kp = brow + i*8;
        rb[i] = (kp < 2*NN) ? *(const float4*)(Ub + (long)kp*CT + n0 + bcol) : fz;
    }
    #pragma unroll
    for (int i = 0; i < 2; i++) {
        float* ap = &As[0][acol][arow + i*64];
        ap[0] = ra[i].x; ap[132] = ra[i].y; ap[264] = ra[i].z; ap[396] = ra[i].w;
        *(float4*)&Bs[0][brow + i*8][bcol] = rb[i];
    }
    __syncthreads();
    int ty = tid >> 4, tx = tid & 15;
    float acc[8][8] = {};
    for (int step = 0; step < 39; step++) {
        if (step < 38) {
            int kk = (step + 1) * 16;
            #pragma unroll
            for (int i = 0; i < 2; i++) {
                int row = m0 + arow + i*64;
                ra[i] = (row < NN) ? *(const float4*)(Ab + (long)row*KP + kk + acol) : fz;
                int kp = kk + brow + i*8;
                rb[i] = (kp < 2*NN) ? *(const float4*)(Ub + (long)kp*CT + n0 + bcol) : fz;
            }
        }
        int buf = step & 1;
        #pragma unroll
        for (int k = 0; k < 16; k++) {
            float a[8], bb[8];
            *(float4*)&a[0]  = *(const float4*)&As[buf][k][ty*8];
            *(float4*)&a[4]  = *(const float4*)&As[buf][k][ty*8 + 4];
            *(float4*)&bb[0] = *(const float4*)&Bs[buf][k][tx*8];
            *(float4*)&bb[4] = *(const float4*)&Bs[buf][k][tx*8 + 4];
            #pragma unroll
            for (int i = 0; i < 8; i++)
                #pragma unroll
                for (int j = 0; j < 8; j++) acc[i][j] += a[i]*bb[j];
        }
        if (step < 38) {
            int nb = buf ^ 1;
            #pragma unroll
            for (int i = 0; i < 2; i++) {
                float* ap = &As[nb][acol][arow + i*64];
                ap[0] = ra[i].x; ap[132] = ra[i].y; ap[264] = ra[i].z; ap[396] = ra[i].w;
                *(float4*)&Bs[nb][brow + i*8][bcol] = rb[i];
            }
        }
        __syncthreads();
    }
    const float* Sb  = g_S  + (long)b*N2;
    const float* U0b = g_U0 + (long)b*NN*CT;
    float* sgb = g_sg + (long)b*NN*CT;
    #pragma unroll
    for (int i = 0; i < 8; i++) {
        int q = m0 + ty*8 + i;
        if (q >= NN) continue;
        float sd = Sb[(long)q*NN + q];
        const float* u0r = U0b + (long)q*CT;
        float* sgr = sgb + (long)q*CT;
        #pragma unroll
        for (int j = 0; j < 8; j++) {
            int cidx = n0 + tx*8 + j;
            float v = acc[i][j] + sd*u0r[cidx] + __ldg(&gcnb[cidx/TT]);
            sgr[cidx] = fmaxf(v, 0.f);
        }
    }
}

// ---------------- tconv + residual conv + relu + LN partials ----------
#define TCN 2
__global__ __launch_bounds__(256) void tconv_kernel(
    const float* __restrict__ x,
    const float* __restrict__ c1w, const float* __restrict__ c1b,
    const float* __restrict__ tcw, const float* __restrict__ tcb) {
    int b = blockIdx.y;
    int n0 = blockIdx.x*TCN;
    __shared__ float ss[TCN][CC][28];
    __shared__ float xs[TCN][CT];
    __shared__ float redS[TCN][4], redQ[TCN][4];
    int tid = threadIdx.x;
    int g = tid >> 7;       // 0..1
    int lane = tid & 127;
    int n = n0 + g;
    if (n < NN) {
        const float* sgb = g_sg + ((long)b*NN + n)*CT;
        for (int i = lane; i < CT; i += 128) {
            int c = i / TT, t = i % TT;
            ss[g][c][t + 1] = sgb[i];
        }
        if (lane < CC) { ss[g][lane][0] = 0.f; ss[g][lane][25] = 0.f; }
        for (int i = lane; i < CT; i += 128) {
            int c = i / TT, t = i % TT;
            xs[g][i] = x[((long)(b*CC + c)*NN + n)*TT + t];
        }
    }
    __syncthreads();
    int og = lane >> 2;          // 0..31
    int t0 = (lane & 3) * 6;
    float acc[2][6];
    #pragma unroll
    for (int i = 0; i < 2; i++) {
        int o = og*2 + i;
        float bias = __ldg(&tcb[o]) + __ldg(&c1b[o]);
        #pragma unroll
        for (int j = 0; j < 6; j++) acc[i][j] = bias;
    }
    float lsum = 0.f, lsq = 0.f;
    if (n < NN) {
        for (int c = 0; c < CC; c++) {
            float s[8];
            #pragma unroll
            for (int j = 0; j < 8; j++) s[j] = ss[g][c][t0 + j];
            float xv[6];
            #pragma unroll
            for (int j = 0; j < 6; j++) xv[j] = xs[g][c*TT + t0 + j];
            #pragma unroll
            for (int i = 0; i < 2; i++) {
                int o = og*2 + i;
                float w0 = __ldg(&tcw[o*192 + c*3 + 0]);
                float w1 = __ldg(&tcw[o*192 + c*3 + 1]);
                float w2 = __ldg(&tcw[o*192 + c*3 + 2]);
                float cw = __ldg(&c1w[o*CC + c]);
                #pragma unroll
                for (int j = 0; j < 6; j++)
                    acc[i][j] += w0*s[j] + w1*s[j+1] + w2*s[j+2] + cw*xv[j];
            }
        }
        #pragma unroll
        for (int i = 0; i < 2; i++) {
            int o = og*2 + i;
            float* hp = g_h + ((long)(b*CC + o)*NN + n)*TT + t0;
            #pragma unroll
            for (int j = 0; j < 6; j++) {
                float h = fmaxf(acc[i][j], 0.f);
                hp[j] = h;
                lsum += h; lsq += h*h;
            }
        }
    }
    #pragma unroll
    for (int o2 = 16; o2 > 0; o2 >>= 1) {
        lsum += __shfl_down_sync(0xffffffffu, lsum, o2);
        lsq  += __shfl_down_sync(0xffffffffu, lsq,  o2);
    }
    if ((lane & 31) == 0) { redS[g][lane >> 5] = lsum; redQ[g][lane >> 5] = lsq; }
    __syncthreads();
    if (lane == 0 && n < NN) {
        float s = 0.f, q2 = 0.f;
        #pragma unroll
        for (int w = 0; w < 4; w++) { s += redS[g][w]; q2 += redQ[g][w]; }
        g_part[b][n][0] = s; g_part[b][n][1] = q2;
    }
}

// ---------------- LN stats + apply ----------------
__global__ void stats_kernel() {
    int b = blockIdx.x; int tid = threadIdx.x;
    __shared__ float rs[256], rq[256];
    float s = 0.f, q = 0.f;
    for (int n = tid; n < NN; n += 256) { s += g_part[b][n][0]; q += g_part[b][n][1]; }
    rs[tid] = s; rq[tid] = q; __syncthreads();
    for (int o = 128; o > 0; o >>= 1) {
        if (tid < o) { rs[tid] += rs[tid + o]; rq[tid] += rq[tid + o]; }
        __syncthreads();
    }
    if (tid == 0) {
        float mu = rs[0] / (float)CNT;
        float var = rq[0] / (float)CNT - mu*mu;
        g_stats[b][0] = mu;
        g_stats[b][1] = rsqrtf(var + 1e-5f);
    }
}

__global__ void ln_kernel(const float* __restrict__ lng,
                          const float* __restrict__ lnb,
                          float* __restrict__ out) {
    long idx = (long)blockIdx.x*256 + threadIdx.x;
    if (idx >= OUT0) return;
    int b = (int)(idx / CNT);
    int r = (int)(idx % CNT);
    float mu = g_stats[b][0], rstd = g_stats[b][1];
    out[idx] = (g_h[idx] - mu)*rstd*__ldg(&lng[r]) + __ldg(&lnb[r]);
}

// ---------------- launch ----------------
extern "C" void kernel_launch(void* const* d_in, const int* in_sizes, int n_in,
                              void* d_out, int out_size) {
    const float* x       = (const float*)d_in[0];
    const float* supports= (const float*)d_in[1];
    const float* conv1_w = (const float*)d_in[2];
    const float* conv1_b = (const float*)d_in[3];
    const float* t_c1    = (const float*)d_in[4];
    const float* t_c2    = (const float*)d_in[5];
    const float* t_w     = (const float*)d_in[6];
    const float* t_b     = (const float*)d_in[7];
    const float* t_v     = (const float*)d_in[8];
    const float* s_c1    = (const float*)d_in[9];
    const float* s_c2    = (const float*)d_in[10];
    const float* s_w     = (const float*)d_in[11];
    const float* s_b     = (const float*)d_in[12];
    const float* s_v     = (const float*)d_in[13];
    const float* gcn_w   = (const float*)d_in[14];
    const float* gcn_b   = (const float*)d_in[15];
    const float* tc_w    = (const float*)d_in[16];
    const float* tc_b    = (const float*)d_in[17];
    const float* ln_g    = (const float*)d_in[18];
    const float* ln_b    = (const float*)d_in[19];
    float* out = (float*)d_out;
    long osz = (long)out_size;

    // features
    feat_c_kernel <<<(BN*NT + 255)/256, 256>>>(x, t_c1, s_c1);
    feat_f2_kernel<<<dim3(CC, BN), 256>>>(x, t_c2);
    feat_g2_kernel<<<(BN*CC*NN + 255)/256, 256>>>(x, s_c2);

    // temporal attention
    tatt_kernel<<<BN, 256>>>(t_w, t_b, t_v, out, osz);

    // spatial attention
    satt_E_kernel<<<(BN*NN*CC + 255)/256, 256>>>(s_w);
    dim3 gz((NN + 63)/64, (NN + 63)/64, BN);
    gemm_Z_kernel <<<gz, 256>>>(s_b);
    gemm_Z2_kernel<<<gz, 256>>>(s_v);
    colmax_kernel<<<BN, 320>>>();
    softmax_kernel<<<dim3(NN, BN), 128>>>(out, osz);

    // Chebyshev L2
    dim3 gc((NN + 63)/64, (NN + 63)/64, 1);
    gemm_cheb_kernel<<<gc, 256>>>(supports);

    // Acat precompute
    {
        long total = (long)BN*NN*KP;
        acat_kernel<<<(int)((total + 255)/256), 256>>>(supports);
    }

    // fused x_TAt + U
    xtat_u_kernel<<<dim3(NN, BN), 256>>>(x, gcn_w);

    // big graph GEMM: per-b [307 x 614] @ [614 x 1536], fused epilogue
    dim3 gg(CT/128, (NN + 127)/128, BN);
    gemm_graph_kernel<<<gg, 256>>>(gcn_b);

    // tconv + residual + relu + LN partials
    tconv_kernel<<<dim3((NN + TCN - 1)/TCN, BN), 256>>>(x, conv1_w, conv1_b, tc_w, tc_b);

    // LayerNorm
    stats_kernel<<<BN, 256>>>();
    ln_kernel<<<(int)((OUT0 + 255)/256), 256>>>(ln_g, ln_b, out);
}